// round 1
// baseline (speedup 1.0000x reference)
#include <cuda_runtime.h>
#include <math.h>
#include <float.h>

// Problem constants (fixed shapes)
#define NN   64000      // nodes
#define NPGc 500        // nodes per graph
#define GG   128        // graphs
#define EE   131072     // edges
#define DIN  768        // input dim
#define HH   512        // hidden
#define CC   4          // classes
#define KKc  250        // kept nodes per graph
#define EPSc 1e-5f

// ---------------- scratch (static device globals; no allocation) -------------
__device__ float d_deg[NN];            // deg -> dinv (in place)
__device__ float d_h0[NN * HH];        // x @ gcn_w
__device__ float d_h [NN * HH];        // agg accumulator -> final h (relu'd)
__device__ float d_s2[NN];             // h @ sag_w2 (per node)
__device__ float d_s [NN];             // final scores
__device__ int   d_gidx[GG * KKc];     // selected global node ids
__device__ float d_tval[GG * KKc];     // tanh(score) gates
__device__ float d_S  [GG * HH];       // per-graph feature sums of xp
__device__ float d_ssq[HH];            // global sum of xp^2 per feature

// ---------------- init ----------------
__global__ void init_kernel() {
    int i = blockIdx.x * blockDim.x + threadIdx.x;
    if (i < NN) d_deg[i] = 1.0f;       // self-loop
    if (i < HH) d_ssq[i] = 0.0f;
}

__global__ void zero_h_kernel() {
    int i = blockIdx.x * blockDim.x + threadIdx.x;   // NN*HH/4 threads
    ((float4*)d_h)[i] = make_float4(0.f, 0.f, 0.f, 0.f);
}

// ---------------- degree ----------------
__global__ void deg_kernel(const int* __restrict__ dst) {
    int e = blockIdx.x * blockDim.x + threadIdx.x;
    if (e < EE) atomicAdd(&d_deg[dst[e]], 1.0f);
}

__global__ void dinv_kernel() {
    int i = blockIdx.x * blockDim.x + threadIdx.x;
    if (i < NN) d_deg[i] = rsqrtf(d_deg[i]);   // now holds deg^{-1/2}
}

// ---------------- SGEMM: h0 = x[NN,DIN] @ W[DIN,HH] ----------------
// 128x128 block tile, 8x8 per thread, K-step 8. All dims divide exactly.
__global__ __launch_bounds__(256) void gemm_kernel(
    const float* __restrict__ A, const float* __restrict__ B) {
    __shared__ float As[8][128];
    __shared__ float Bs[8][128];

    const int tid = threadIdx.x;
    const int m0 = blockIdx.y * 128;
    const int n0 = blockIdx.x * 128;
    const int tr = tid >> 4;          // 0..15
    const int tc = tid & 15;          // 0..15

    const int aRow = tid >> 1;        // 0..127
    const int aCol = (tid & 1) * 4;   // 0 or 4
    const int bR   = tid >> 5;        // 0..7
    const int bC   = (tid & 31) * 4;  // 0..124

    float acc[8][8];
    #pragma unroll
    for (int i = 0; i < 8; i++)
        #pragma unroll
        for (int j = 0; j < 8; j++) acc[i][j] = 0.f;

    for (int k0 = 0; k0 < DIN; k0 += 8) {
        float4 av = *(const float4*)&A[(size_t)(m0 + aRow) * DIN + k0 + aCol];
        As[aCol + 0][aRow] = av.x;
        As[aCol + 1][aRow] = av.y;
        As[aCol + 2][aRow] = av.z;
        As[aCol + 3][aRow] = av.w;
        float4 bv = *(const float4*)&B[(size_t)(k0 + bR) * HH + n0 + bC];
        *(float4*)&Bs[bR][bC] = bv;
        __syncthreads();

        #pragma unroll
        for (int kk = 0; kk < 8; kk++) {
            float a[8], b[8];
            #pragma unroll
            for (int i = 0; i < 8; i++) a[i] = As[kk][tr * 8 + i];
            #pragma unroll
            for (int j = 0; j < 8; j++) b[j] = Bs[kk][tc * 8 + j];
            #pragma unroll
            for (int i = 0; i < 8; i++)
                #pragma unroll
                for (int j = 0; j < 8; j++) acc[i][j] += a[i] * b[j];
        }
        __syncthreads();
    }

    #pragma unroll
    for (int i = 0; i < 8; i++) {
        float* out = &d_h0[(size_t)(m0 + tr * 8 + i) * HH + n0 + tc * 8];
        #pragma unroll
        for (int j = 0; j < 8; j += 4)
            *(float4*)&out[j] = make_float4(acc[i][j], acc[i][j+1], acc[i][j+2], acc[i][j+3]);
    }
}

// ---------------- edge aggregation: agg[dst] += h0[src] * dinv[s]*dinv[d] ----
__global__ void agg_kernel(const int* __restrict__ src, const int* __restrict__ dst) {
    __shared__ int sS, sD;
    __shared__ float sC;
    int e = blockIdx.x;
    if (threadIdx.x == 0) {
        int s = src[e], d = dst[e];
        sS = s; sD = d;
        sC = d_deg[s] * d_deg[d];
    }
    __syncthreads();
    int f = threadIdx.x * 4;
    float4 hv = *(const float4*)&d_h0[(size_t)sS * HH + f];
    float c = sC;
    float* out = &d_h[(size_t)sD * HH + f];
    atomicAdd(&out[0], hv.x * c);
    atomicAdd(&out[1], hv.y * c);
    atomicAdd(&out[2], hv.z * c);
    atomicAdd(&out[3], hv.w * c);
}

// ---------------- h = relu(agg + h0*dinv^2 + b) ----------------
__global__ void finalize_h_kernel(const float* __restrict__ gcn_b) {
    int i4 = blockIdx.x * blockDim.x + threadIdx.x;  // NN*HH/4 threads
    int base = i4 * 4;
    int n = base >> 9;      // /512
    int f = base & 511;
    float di = d_deg[n];
    float d2 = di * di;
    float4 a  = ((const float4*)d_h)[i4];
    float4 h0 = ((const float4*)d_h0)[i4];
    float4 b  = *(const float4*)&gcn_b[f];
    float4 r;
    r.x = fmaxf(a.x + h0.x * d2 + b.x, 0.f);
    r.y = fmaxf(a.y + h0.y * d2 + b.y, 0.f);
    r.z = fmaxf(a.z + h0.z * d2 + b.z, 0.f);
    r.w = fmaxf(a.w + h0.w * d2 + b.w, 0.f);
    ((float4*)d_h)[i4] = r;
}

// ---------------- per-node score dots: s = h.w1 + b ; s2 = h.w2 -------------
__global__ __launch_bounds__(256) void score_dot_kernel(
    const float* __restrict__ w1, const float* __restrict__ w2,
    const float* __restrict__ sag_b) {
    __shared__ float sw1[HH], sw2[HH];
    int tid = threadIdx.x;
    sw1[tid] = w1[tid];         sw2[tid] = w2[tid];
    sw1[tid + 256] = w1[tid + 256]; sw2[tid + 256] = w2[tid + 256];
    __syncthreads();

    int warp = tid >> 5, lane = tid & 31;
    int n = blockIdx.x * 8 + warp;
    const float* hr = &d_h[(size_t)n * HH];
    float a = 0.f, b = 0.f;
    #pragma unroll
    for (int f = lane; f < HH; f += 32) {
        float hv = hr[f];
        a += hv * sw1[f];
        b += hv * sw2[f];
    }
    #pragma unroll
    for (int o = 16; o > 0; o >>= 1) {
        a += __shfl_down_sync(0xffffffffu, a, o);
        b += __shfl_down_sync(0xffffffffu, b, o);
    }
    if (lane == 0) {
        d_s[n]  = a + sag_b[0];
        d_s2[n] = b;
    }
}

__global__ void score_edge_kernel(const int* __restrict__ src, const int* __restrict__ dst) {
    int e = blockIdx.x * blockDim.x + threadIdx.x;
    if (e < EE) atomicAdd(&d_s[dst[e]], d_s2[src[e]]);
}

// ---------------- per-graph top-250 of 500 (bitonic, stable ties) -----------
__global__ __launch_bounds__(256) void topk_kernel() {
    __shared__ float key[512];
    __shared__ int   kid[512];
    int g = blockIdx.x;
    for (int i = threadIdx.x; i < 512; i += 256) {
        if (i < NPGc) { key[i] = d_s[g * NPGc + i]; kid[i] = i; }
        else          { key[i] = -FLT_MAX;          kid[i] = i; }
    }
    for (int k = 2; k <= 512; k <<= 1) {
        for (int j = k >> 1; j > 0; j >>= 1) {
            __syncthreads();
            for (int t = threadIdx.x; t < 512; t += 256) {
                int p = t ^ j;
                if (p > t) {
                    float ka = key[t], kb = key[p];
                    int   ia = kid[t], ib = kid[p];
                    bool b_gt_a = (kb > ka) || (kb == ka && ib < ia);
                    bool desc = ((t & k) == 0);
                    // desc region wants a >= b ; asc region wants a <= b
                    bool do_swap = desc ? b_gt_a : (!b_gt_a && (ka != kb || ia != ib));
                    if (do_swap) {
                        key[t] = kb; key[p] = ka;
                        kid[t] = ib; kid[p] = ia;
                    }
                }
            }
        }
    }
    __syncthreads();
    for (int i = threadIdx.x; i < KKc; i += 256) {
        d_gidx[g * KKc + i] = g * NPGc + kid[i];
        d_tval[g * KKc + i] = tanhf(key[i]);
    }
}

// ---------------- pooled sums + global sum of squares -----------------------
__global__ __launch_bounds__(256) void pool_kernel() {
    __shared__ int   sg[KKc];
    __shared__ float st[KKc];
    int g = blockIdx.x;
    int tid = threadIdx.x;
    if (tid < KKc) { sg[tid] = d_gidx[g * KKc + tid]; st[tid] = d_tval[g * KKc + tid]; }
    __syncthreads();

    int f1 = tid, f2 = tid + 256;
    float s1 = 0.f, q1 = 0.f, s2 = 0.f, q2 = 0.f;
    for (int k = 0; k < KKc; k++) {
        const float* hr = &d_h[(size_t)sg[k] * HH];
        float t = st[k];
        float v1 = hr[f1] * t;
        float v2 = hr[f2] * t;
        s1 += v1; q1 += v1 * v1;
        s2 += v2; q2 += v2 * v2;
    }
    d_S[g * HH + f1] = s1;
    d_S[g * HH + f2] = s2;
    atomicAdd(&d_ssq[f1], q1);
    atomicAdd(&d_ssq[f2], q2);
}

// ---------------- BN (fused) + mean-pool + FC + log_softmax -----------------
__global__ __launch_bounds__(512) void final_kernel(
    const float* __restrict__ gamma, const float* __restrict__ beta,
    const float* __restrict__ fc_w,  const float* __restrict__ fc_b,
    float* __restrict__ out) {
    __shared__ float mu[HH], rstd[HH], lg[GG * CC];
    int tid = threadIdx.x;

    // per-feature stats over all G*K rows
    {
        int f = tid;
        float cs = 0.f;
        for (int g = 0; g < GG; g++) cs += d_S[g * HH + f];
        float m = cs * (1.0f / (GG * KKc));
        float var = d_ssq[f] * (1.0f / (GG * KKc)) - m * m;
        mu[f] = m;
        rstd[f] = rsqrtf(var + EPSc);
    }
    __syncthreads();

    // logits: one thread per (g, c)
    {
        int g = tid >> 2, c = tid & 3;
        float acc = fc_b[c];
        for (int f = 0; f < HH; f++) {
            float pooled = (d_S[g * HH + f] * (1.0f / KKc) - mu[f]) * rstd[f] * gamma[f] + beta[f];
            acc += pooled * fc_w[f * CC + c];
        }
        lg[tid] = acc;
    }
    __syncthreads();

    if (tid < GG) {
        float l0 = lg[tid * 4 + 0], l1 = lg[tid * 4 + 1];
        float l2 = lg[tid * 4 + 2], l3 = lg[tid * 4 + 3];
        float m = fmaxf(fmaxf(l0, l1), fmaxf(l2, l3));
        float lse = m + logf(expf(l0 - m) + expf(l1 - m) + expf(l2 - m) + expf(l3 - m));
        out[tid * 4 + 0] = l0 - lse;
        out[tid * 4 + 1] = l1 - lse;
        out[tid * 4 + 2] = l2 - lse;
        out[tid * 4 + 3] = l3 - lse;
    }
}

// ---------------- launch ----------------
extern "C" void kernel_launch(void* const* d_in, const int* in_sizes, int n_in,
                              void* d_out, int out_size) {
    const float* x      = (const float*)d_in[0];
    const float* gcn_w  = (const float*)d_in[1];
    const float* gcn_b  = (const float*)d_in[2];
    const float* sag_w1 = (const float*)d_in[3];
    const float* sag_w2 = (const float*)d_in[4];
    const float* sag_b  = (const float*)d_in[5];
    const float* bn_g   = (const float*)d_in[6];
    const float* bn_b   = (const float*)d_in[7];
    const float* fc_w   = (const float*)d_in[8];
    const float* fc_b   = (const float*)d_in[9];
    const int*   ei     = (const int*)d_in[10];   // [2, E] int32
    // d_in[11] = batch (unused; graphs are contiguous NPG blocks)
    const int* src = ei;
    const int* dst = ei + EE;
    float* out = (float*)d_out;

    init_kernel<<<(NN + 255) / 256, 256>>>();
    zero_h_kernel<<<(NN * HH / 4) / 256, 256>>>();
    deg_kernel<<<(EE + 255) / 256, 256>>>(dst);
    dinv_kernel<<<(NN + 255) / 256, 256>>>();
    gemm_kernel<<<dim3(HH / 128, NN / 128), 256>>>(x, gcn_w);
    agg_kernel<<<EE, 128>>>(src, dst);
    finalize_h_kernel<<<(NN * HH / 4) / 256, 256>>>(gcn_b);
    score_dot_kernel<<<NN / 8, 256>>>(sag_w1, sag_w2, sag_b);
    score_edge_kernel<<<(EE + 255) / 256, 256>>>(src, dst);
    topk_kernel<<<GG, 256>>>();
    pool_kernel<<<GG, 256>>>();
    final_kernel<<<1, 512>>>(bn_g, bn_b, fc_w, fc_b, out);
}

// round 5
// speedup vs baseline: 1.6985x; 1.6985x over previous
#include <cuda_runtime.h>
#include <cuda_bf16.h>
#include <math.h>
#include <float.h>
#include <stdint.h>

// Problem constants (fixed shapes)
#define NN   64000      // nodes
#define NPGc 500        // nodes per graph
#define GG   128        // graphs
#define EE   131072     // edges
#define DIN  768        // input dim
#define HH   512        // hidden
#define CC   4          // classes
#define KKc  250        // kept nodes per graph
#define EPSc 1e-5f

// split-GEMM config: K' = 3 * 768 = 2304 = 36 chunks of 64 bf16
#define KSPLIT   1536   // row stride of split buffers (hi 768 | lo 768)
#define NCHUNK   36
#define STAGES   3

// ---------------- scratch (static device globals; no allocation) -------------
__device__ float d_deg[NN];
__device__ float d_h0[NN * HH];
__device__ float d_h [NN * HH];
__device__ float d_s2[NN];
__device__ float d_s [NN];
__device__ int   d_gidx[GG * KKc];
__device__ float d_tval[GG * KKc];
__device__ float d_S  [GG * HH];
__device__ float d_ssq[HH];
__device__ __nv_bfloat16 d_xs[(size_t)NN * KSPLIT];   // x split: [m][hi 768 | lo 768]
__device__ __nv_bfloat16 d_ws[(size_t)HH * KSPLIT];   // W^T split: [n][hi 768 | lo 768]

__device__ __forceinline__ uint32_t smem_u32(const void* p) {
    uint32_t a;
    asm("{ .reg .u64 t; cvta.to.shared.u64 t, %1; cvt.u32.u64 %0, t; }" : "=r"(a) : "l"(p));
    return a;
}

__device__ __forceinline__ void cp_async16(uint32_t dst, const void* src) {
    asm volatile("cp.async.cg.shared.global [%0], [%1], 16;" :: "r"(dst), "l"(src));
}

// ---------------- split conversion ----------------
__global__ void convert_x_kernel(const float* __restrict__ x) {
    int i = blockIdx.x * blockDim.x + threadIdx.x;   // NN*DIN threads
    int m = i / DIN, k = i - m * DIN;
    float v = x[i];
    __nv_bfloat16 hi = __float2bfloat16(v);
    __nv_bfloat16 lo = __float2bfloat16(v - __bfloat162float(hi));
    d_xs[(size_t)m * KSPLIT + k] = hi;
    d_xs[(size_t)m * KSPLIT + DIN + k] = lo;
}

__global__ void convert_w_kernel(const float* __restrict__ w) {
    int i = blockIdx.x * blockDim.x + threadIdx.x;   // DIN*HH threads
    int k = i / HH, n = i - k * HH;
    float v = w[i];
    __nv_bfloat16 hi = __float2bfloat16(v);
    __nv_bfloat16 lo = __float2bfloat16(v - __bfloat162float(hi));
    d_ws[(size_t)n * KSPLIT + k] = hi;
    d_ws[(size_t)n * KSPLIT + DIN + k] = lo;
}

// ---------------- HMMA GEMM: h0 = x @ W  (bf16 split 3-product) -------------
// CTA tile 128(M) x 128(N), BK=64 (one split chunk). 8 warps: 2(M) x 4(N),
// warp tile 64x32 = 4 m16 x 4 n8 mma frags. SMEM XOR-swizzled 128B rows.
#define STAGE_BYTES 32768          // A 16KB + B 16KB
#define SMEM_TOTAL_GEMM (STAGES * STAGE_BYTES)

__device__ __forceinline__ void load_stage(uint32_t sb, int stage, int c, int m0, int n0) {
    // chunk -> K offsets for the 3 products: hh, hl, lh
    int a_off = (c < 12) ? c * 64 : ((c < 24) ? (c - 12) * 64 : DIN + (c - 24) * 64);
    int b_off = (c < 12) ? c * 64 : ((c < 24) ? DIN + (c - 12) * 64 : (c - 24) * 64);
    uint32_t abase = sb + stage * STAGE_BYTES;
    uint32_t bbase = abase + 16384;
    int tid = threadIdx.x;
    #pragma unroll
    for (int i = 0; i < 4; i++) {
        int idx = tid + i * 256;          // 0..1023
        int r = idx >> 3, t = idx & 7;
        uint32_t sw = (uint32_t)((t ^ (r & 7)) << 4);
        cp_async16(abase + r * 128 + sw, d_xs + (size_t)(m0 + r) * KSPLIT + a_off + t * 8);
        cp_async16(bbase + r * 128 + sw, d_ws + (size_t)(n0 + r) * KSPLIT + b_off + t * 8);
    }
}

__device__ __forceinline__ void ldmx4(uint32_t& r0, uint32_t& r1, uint32_t& r2,
                                      uint32_t& r3, uint32_t addr) {
    asm volatile("ldmatrix.sync.aligned.m8n8.x4.shared.b16 {%0,%1,%2,%3}, [%4];"
                 : "=r"(r0), "=r"(r1), "=r"(r2), "=r"(r3) : "r"(addr));
}

__device__ __forceinline__ void mma16816(float* c, const uint32_t* a, const uint32_t* b) {
    asm volatile(
        "mma.sync.aligned.m16n8k16.row.col.f32.bf16.bf16.f32 "
        "{%0,%1,%2,%3}, {%4,%5,%6,%7}, {%8,%9}, {%0,%1,%2,%3};"
        : "+f"(c[0]), "+f"(c[1]), "+f"(c[2]), "+f"(c[3])
        : "r"(a[0]), "r"(a[1]), "r"(a[2]), "r"(a[3]), "r"(b[0]), "r"(b[1]));
}

__global__ __launch_bounds__(256) void gemm_mma_kernel() {
    extern __shared__ __align__(1024) char smem[];
    uint32_t sb = smem_u32(smem);
    const int tid  = threadIdx.x;
    const int wid  = tid >> 5, lane = tid & 31;
    const int n0 = blockIdx.x * 128;
    const int m0 = blockIdx.y * 128;
    const int wm = (wid & 1) * 64;        // warp M offset
    const int wn = (wid >> 1) * 32;       // warp N offset

    // lane-derived ldmatrix row selectors
    const int q  = lane >> 3;             // matrix index 0..3
    const int rq = lane & 7;              // row within 8x8 matrix
    const int a_rowl   = (q & 1) * 8 + rq;   // A: row-local within m16
    const int a_chunkq = q >> 1;             // A: k8 selector
    const int b_rowl   = (q >> 1) * 8 + rq;  // B: n-local within n16
    const int b_chunkq = q & 1;              // B: k8 selector

    float acc[4][4][4];
    #pragma unroll
    for (int i = 0; i < 4; i++)
        #pragma unroll
        for (int j = 0; j < 4; j++)
            #pragma unroll
            for (int v = 0; v < 4; v++) acc[i][j][v] = 0.f;

    // prologue: fill 3 stages
    #pragma unroll
    for (int p = 0; p < STAGES; ++p) {
        load_stage(sb, p, p, m0, n0);
        asm volatile("cp.async.commit_group;" ::: "memory");
    }

    for (int c = 0; c < NCHUNK; ++c) {
        int s = c % STAGES;
        asm volatile("cp.async.wait_group 2;" ::: "memory");
        __syncthreads();
        uint32_t Ab = sb + s * STAGE_BYTES;
        uint32_t Bb = Ab + 16384;

        #pragma unroll
        for (int ks = 0; ks < 4; ++ks) {
            uint32_t a[4][4];
            uint32_t b[4][2];
            #pragma unroll
            for (int mi = 0; mi < 4; ++mi) {
                int row = wm + mi * 16 + a_rowl;
                uint32_t addr = Ab + row * 128 +
                                (uint32_t)(((ks * 2 + a_chunkq) ^ (row & 7)) << 4);
                ldmx4(a[mi][0], a[mi][1], a[mi][2], a[mi][3], addr);
            }
            #pragma unroll
            for (int nj = 0; nj < 2; ++nj) {
                int n = wn + nj * 16 + b_rowl;
                uint32_t addr = Bb + n * 128 +
                                (uint32_t)(((ks * 2 + b_chunkq) ^ (n & 7)) << 4);
                uint32_t r0, r1, r2, r3;
                ldmx4(r0, r1, r2, r3, addr);
                b[nj * 2 + 0][0] = r0; b[nj * 2 + 0][1] = r1;
                b[nj * 2 + 1][0] = r2; b[nj * 2 + 1][1] = r3;
            }
            #pragma unroll
            for (int mi = 0; mi < 4; ++mi)
                #pragma unroll
                for (int nj = 0; nj < 4; ++nj)
                    mma16816(acc[mi][nj], a[mi], b[nj]);
        }
        __syncthreads();
        int cn = c + STAGES;
        if (cn < NCHUNK) load_stage(sb, s, cn, m0, n0);
        asm volatile("cp.async.commit_group;" ::: "memory");
    }

    // epilogue: thread holds (row lane/4 [+8], cols (lane%4)*2 {+0,1})
    const int erow = lane >> 2;
    const int ecol = (lane & 3) * 2;
    #pragma unroll
    for (int mi = 0; mi < 4; ++mi) {
        #pragma unroll
        for (int nj = 0; nj < 4; ++nj) {
            int gr = m0 + wm + mi * 16 + erow;
            int gc = n0 + wn + nj * 8 + ecol;
            float* o0 = &d_h0[(size_t)gr * HH + gc];
            o0[0] = acc[mi][nj][0];
            o0[1] = acc[mi][nj][1];
            float* o1 = &d_h0[(size_t)(gr + 8) * HH + gc];
            o1[0] = acc[mi][nj][2];
            o1[1] = acc[mi][nj][3];
        }
    }
}

// ---------------- init ----------------
__global__ void init_kernel() {
    int i = blockIdx.x * blockDim.x + threadIdx.x;
    if (i < NN) d_deg[i] = 1.0f;
    if (i < HH) d_ssq[i] = 0.0f;
}

__global__ void zero_h_kernel() {
    int i = blockIdx.x * blockDim.x + threadIdx.x;
    ((float4*)d_h)[i] = make_float4(0.f, 0.f, 0.f, 0.f);
}

__global__ void deg_kernel(const int* __restrict__ dst) {
    int e = blockIdx.x * blockDim.x + threadIdx.x;
    if (e < EE) atomicAdd(&d_deg[dst[e]], 1.0f);
}

__global__ void dinv_kernel() {
    int i = blockIdx.x * blockDim.x + threadIdx.x;
    if (i < NN) d_deg[i] = rsqrtf(d_deg[i]);
}

// ---------------- edge aggregation ----------------
__global__ void agg_kernel(const int* __restrict__ src, const int* __restrict__ dst) {
    __shared__ int sS, sD;
    __shared__ float sC;
    int e = blockIdx.x;
    if (threadIdx.x == 0) {
        int s = src[e], d = dst[e];
        sS = s; sD = d;
        sC = d_deg[s] * d_deg[d];
    }
    __syncthreads();
    int f = threadIdx.x * 4;
    float4 hv = *(const float4*)&d_h0[(size_t)sS * HH + f];
    float c = sC;
    float* out = &d_h[(size_t)sD * HH + f];
    atomicAdd(&out[0], hv.x * c);
    atomicAdd(&out[1], hv.y * c);
    atomicAdd(&out[2], hv.z * c);
    atomicAdd(&out[3], hv.w * c);
}

__global__ void finalize_h_kernel(const float* __restrict__ gcn_b) {
    int i4 = blockIdx.x * blockDim.x + threadIdx.x;
    int base = i4 * 4;
    int n = base >> 9;
    int f = base & 511;
    float di = d_deg[n];
    float d2 = di * di;
    float4 a  = ((const float4*)d_h)[i4];
    float4 h0 = ((const float4*)d_h0)[i4];
    float4 b  = *(const float4*)&gcn_b[f];
    float4 r;
    r.x = fmaxf(a.x + h0.x * d2 + b.x, 0.f);
    r.y = fmaxf(a.y + h0.y * d2 + b.y, 0.f);
    r.z = fmaxf(a.z + h0.z * d2 + b.z, 0.f);
    r.w = fmaxf(a.w + h0.w * d2 + b.w, 0.f);
    ((float4*)d_h)[i4] = r;
}

// ---------------- score dots ----------------
__global__ __launch_bounds__(256) void score_dot_kernel(
    const float* __restrict__ w1, const float* __restrict__ w2,
    const float* __restrict__ sag_b) {
    __shared__ float sw1[HH], sw2[HH];
    int tid = threadIdx.x;
    sw1[tid] = w1[tid];             sw2[tid] = w2[tid];
    sw1[tid + 256] = w1[tid + 256]; sw2[tid + 256] = w2[tid + 256];
    __syncthreads();

    int warp = tid >> 5, lane = tid & 31;
    int n = blockIdx.x * 8 + warp;
    const float* hr = &d_h[(size_t)n * HH];
    float a = 0.f, b = 0.f;
    #pragma unroll
    for (int f = lane; f < HH; f += 32) {
        float hv = hr[f];
        a += hv * sw1[f];
        b += hv * sw2[f];
    }
    #pragma unroll
    for (int o = 16; o > 0; o >>= 1) {
        a += __shfl_down_sync(0xffffffffu, a, o);
        b += __shfl_down_sync(0xffffffffu, b, o);
    }
    if (lane == 0) {
        d_s[n]  = a + sag_b[0];
        d_s2[n] = b;
    }
}

__global__ void score_edge_kernel(const int* __restrict__ src, const int* __restrict__ dst) {
    int e = blockIdx.x * blockDim.x + threadIdx.x;
    if (e < EE) atomicAdd(&d_s[dst[e]], d_s2[src[e]]);
}

// ---------------- per-graph top-250 of 500 (bitonic, stable ties) -----------
__global__ __launch_bounds__(256) void topk_kernel() {
    __shared__ float key[512];
    __shared__ int   kid[512];
    int g = blockIdx.x;
    for (int i = threadIdx.x; i < 512; i += 256) {
        if (i < NPGc) { key[i] = d_s[g * NPGc + i]; kid[i] = i; }
        else          { key[i] = -FLT_MAX;          kid[i] = i; }
    }
    for (int k = 2; k <= 512; k <<= 1) {
        for (int j = k >> 1; j > 0; j >>= 1) {
            __syncthreads();
            for (int t = threadIdx.x; t < 512; t += 256) {
                int p = t ^ j;
                if (p > t) {
                    float ka = key[t], kb = key[p];
                    int   ia = kid[t], ib = kid[p];
                    bool b_gt_a = (kb > ka) || (kb == ka && ib < ia);
                    bool desc = ((t & k) == 0);
                    bool do_swap = desc ? b_gt_a : (!b_gt_a && (ka != kb || ia != ib));
                    if (do_swap) {
                        key[t] = kb; key[p] = ka;
                        kid[t] = ib; kid[p] = ia;
                    }
                }
            }
        }
    }
    __syncthreads();
    for (int i = threadIdx.x; i < KKc; i += 256) {
        d_gidx[g * KKc + i] = g * NPGc + kid[i];
        d_tval[g * KKc + i] = tanhf(key[i]);
    }
}

// ---------------- pooled sums + global sum of squares -----------------------
__global__ __launch_bounds__(256) void pool_kernel() {
    __shared__ int   sg[KKc];
    __shared__ float st[KKc];
    int g = blockIdx.x;
    int tid = threadIdx.x;
    if (tid < KKc) { sg[tid] = d_gidx[g * KKc + tid]; st[tid] = d_tval[g * KKc + tid]; }
    __syncthreads();

    int f1 = tid, f2 = tid + 256;
    float s1 = 0.f, q1 = 0.f, s2 = 0.f, q2 = 0.f;
    for (int k = 0; k < KKc; k++) {
        const float* hr = &d_h[(size_t)sg[k] * HH];
        float t = st[k];
        float v1 = hr[f1] * t;
        float v2 = hr[f2] * t;
        s1 += v1; q1 += v1 * v1;
        s2 += v2; q2 += v2 * v2;
    }
    d_S[g * HH + f1] = s1;
    d_S[g * HH + f2] = s2;
    atomicAdd(&d_ssq[f1], q1);
    atomicAdd(&d_ssq[f2], q2);
}

// ---------------- BN (fused) + mean-pool + FC + log_softmax -----------------
__global__ __launch_bounds__(512) void final_kernel(
    const float* __restrict__ gamma, const float* __restrict__ beta,
    const float* __restrict__ fc_w,  const float* __restrict__ fc_b,
    float* __restrict__ out) {
    __shared__ float mu[HH], rstd[HH], lg[GG * CC];
    int tid = threadIdx.x;
    {
        int f = tid;
        float cs = 0.f;
        for (int g = 0; g < GG; g++) cs += d_S[g * HH + f];
        float m = cs * (1.0f / (GG * KKc));
        float var = d_ssq[f] * (1.0f / (GG * KKc)) - m * m;
        mu[f] = m;
        rstd[f] = rsqrtf(var + EPSc);
    }
    __syncthreads();
    {
        int g = tid >> 2, c = tid & 3;
        float acc = fc_b[c];
        for (int f = 0; f < HH; f++) {
            float pooled = (d_S[g * HH + f] * (1.0f / KKc) - mu[f]) * rstd[f] * gamma[f] + beta[f];
            acc += pooled * fc_w[f * CC + c];
        }
        lg[tid] = acc;
    }
    __syncthreads();
    if (tid < GG) {
        float l0 = lg[tid * 4 + 0], l1 = lg[tid * 4 + 1];
        float l2 = lg[tid * 4 + 2], l3 = lg[tid * 4 + 3];
        float m = fmaxf(fmaxf(l0, l1), fmaxf(l2, l3));
        float lse = m + logf(expf(l0 - m) + expf(l1 - m) + expf(l2 - m) + expf(l3 - m));
        out[tid * 4 + 0] = l0 - lse;
        out[tid * 4 + 1] = l1 - lse;
        out[tid * 4 + 2] = l2 - lse;
        out[tid * 4 + 3] = l3 - lse;
    }
}

// ---------------- launch ----------------
extern "C" void kernel_launch(void* const* d_in, const int* in_sizes, int n_in,
                              void* d_out, int out_size) {
    const float* x      = (const float*)d_in[0];
    const float* gcn_w  = (const float*)d_in[1];
    const float* gcn_b  = (const float*)d_in[2];
    const float* sag_w1 = (const float*)d_in[3];
    const float* sag_w2 = (const float*)d_in[4];
    const float* sag_b  = (const float*)d_in[5];
    const float* bn_g   = (const float*)d_in[6];
    const float* bn_b   = (const float*)d_in[7];
    const float* fc_w   = (const float*)d_in[8];
    const float* fc_b   = (const float*)d_in[9];
    const int*   ei     = (const int*)d_in[10];
    const int* src = ei;
    const int* dst = ei + EE;
    float* out = (float*)d_out;

    cudaFuncSetAttribute(gemm_mma_kernel, cudaFuncAttributeMaxDynamicSharedMemorySize,
                         SMEM_TOTAL_GEMM);

    init_kernel<<<(NN + 255) / 256, 256>>>();
    zero_h_kernel<<<(NN * HH / 4) / 256, 256>>>();
    deg_kernel<<<(EE + 255) / 256, 256>>>(dst);
    dinv_kernel<<<(NN + 255) / 256, 256>>>();
    convert_w_kernel<<<(DIN * HH) / 256, 256>>>(gcn_w);
    convert_x_kernel<<<(NN * DIN) / 256, 256>>>(x);
    gemm_mma_kernel<<<dim3(HH / 128, NN / 128), 256, SMEM_TOTAL_GEMM>>>();
    agg_kernel<<<EE, 128>>>(src, dst);
    finalize_h_kernel<<<(NN * HH / 4) / 256, 256>>>(gcn_b);
    score_dot_kernel<<<NN / 8, 256>>>(sag_w1, sag_w2, sag_b);
    score_edge_kernel<<<(EE + 255) / 256, 256>>>(src, dst);
    topk_kernel<<<GG, 256>>>();
    pool_kernel<<<GG, 256>>>();
    final_kernel<<<1, 512>>>(bn_g, bn_b, fc_w, fc_b, out);
}

// round 6
// speedup vs baseline: 1.9682x; 1.1588x over previous
#include <cuda_runtime.h>
#include <cuda_bf16.h>
#include <math.h>
#include <float.h>
#include <stdint.h>

// Problem constants (fixed shapes)
#define NN   64000      // nodes
#define NPGc 500        // nodes per graph
#define GG   128        // graphs
#define EE   131072     // edges
#define DIN  768        // input dim
#define HH   512        // hidden
#define CC   4          // classes
#define KKc  250        // kept nodes per graph
#define EPSc 1e-5f

// split-GEMM config: K' = 3 * 768 = 2304 = 36 chunks of 64 bf16
#define KSPLIT   1536   // row stride of split buffers (hi 768 | lo 768)
#define NCHUNK   36
#define STAGES   3

// ---------------- scratch (static device globals; no allocation) -------------
__device__ float d_dinv[NN];
__device__ int   d_cnt[NN];
__device__ int   d_rowptr[NN + 1];
__device__ int   d_cur[NN];
__device__ int   d_esrc[EE];
__device__ float d_h0[NN * HH];
__device__ float d_h [NN * HH];
__device__ float d_s2[NN];
__device__ float d_s [NN];
__device__ int   d_gidx[GG * KKc];
__device__ float d_tval[GG * KKc];
__device__ float d_S  [GG * HH];
__device__ float d_ssq[HH];
__device__ __nv_bfloat16 d_xs[(size_t)NN * KSPLIT];   // x split: [m][hi 768 | lo 768]
__device__ __nv_bfloat16 d_ws[(size_t)HH * KSPLIT];   // W^T split: [n][hi 768 | lo 768]

__device__ __forceinline__ uint32_t smem_u32(const void* p) {
    uint32_t a;
    asm("{ .reg .u64 t; cvta.to.shared.u64 t, %1; cvt.u32.u64 %0, t; }" : "=r"(a) : "l"(p));
    return a;
}

__device__ __forceinline__ void cp_async16(uint32_t dst, const void* src) {
    asm volatile("cp.async.cg.shared.global [%0], [%1], 16;" :: "r"(dst), "l"(src));
}

// ---------------- init ----------------
__global__ void init_kernel() {
    int i = blockIdx.x * blockDim.x + threadIdx.x;
    if (i < NN) d_cnt[i] = 0;
    if (i < HH) d_ssq[i] = 0.0f;
}

// ---------------- CSR build ----------------
__global__ void csr_count_kernel(const int* __restrict__ dst) {
    int e = blockIdx.x * blockDim.x + threadIdx.x;
    if (e < EE) atomicAdd(&d_cnt[dst[e]], 1);
}

__global__ __launch_bounds__(1024) void csr_scan_kernel() {
    __shared__ int wsum[32];
    __shared__ int chunk_total;
    int tid = threadIdx.x;
    int lane = tid & 31, w = tid >> 5;
    int running = 0;
    for (int base = 0; base < NN; base += 1024) {
        int i = base + tid;
        int v = (i < NN) ? d_cnt[i] : 0;
        int incl = v;
        #pragma unroll
        for (int o = 1; o < 32; o <<= 1) {
            int t = __shfl_up_sync(0xffffffffu, incl, o);
            if (lane >= o) incl += t;
        }
        if (lane == 31) wsum[w] = incl;
        __syncthreads();
        if (w == 0) {
            int s = wsum[lane];
            #pragma unroll
            for (int o = 1; o < 32; o <<= 1) {
                int t = __shfl_up_sync(0xffffffffu, s, o);
                if (lane >= o) s += t;
            }
            wsum[lane] = s;
            if (lane == 31) chunk_total = s;
        }
        __syncthreads();
        int excl = running + (w > 0 ? wsum[w - 1] : 0) + incl - v;
        if (i < NN) {
            d_rowptr[i] = excl;
            d_cur[i]    = excl;
            d_dinv[i]   = rsqrtf(1.0f + (float)v);   // self-loop degree
        }
        running += chunk_total;
        __syncthreads();
    }
    if (tid == 0) d_rowptr[NN] = EE;
}

__global__ void csr_fill_kernel(const int* __restrict__ src, const int* __restrict__ dst) {
    int e = blockIdx.x * blockDim.x + threadIdx.x;
    if (e < EE) {
        int pos = atomicAdd(&d_cur[dst[e]], 1);
        d_esrc[pos] = src[e];
    }
}

// ---------------- split conversion ----------------
__global__ void convert_x_kernel(const float* __restrict__ x) {
    int i = blockIdx.x * blockDim.x + threadIdx.x;   // NN*DIN threads
    int m = i / DIN, k = i - m * DIN;
    float v = x[i];
    __nv_bfloat16 hi = __float2bfloat16(v);
    __nv_bfloat16 lo = __float2bfloat16(v - __bfloat162float(hi));
    d_xs[(size_t)m * KSPLIT + k] = hi;
    d_xs[(size_t)m * KSPLIT + DIN + k] = lo;
}

__global__ void convert_w_kernel(const float* __restrict__ w) {
    int i = blockIdx.x * blockDim.x + threadIdx.x;   // DIN*HH threads
    int k = i / HH, n = i - k * HH;
    float v = w[i];
    __nv_bfloat16 hi = __float2bfloat16(v);
    __nv_bfloat16 lo = __float2bfloat16(v - __bfloat162float(hi));
    d_ws[(size_t)n * KSPLIT + k] = hi;
    d_ws[(size_t)n * KSPLIT + DIN + k] = lo;
}

// ---------------- HMMA GEMM: h0 = x @ W  (bf16 split 3-product) -------------
// CTA tile 128(M) x 256(N), BK=64. 8 warps: 2(M) x 4(N) -> warp tile 64x64.
#define STAGE_BYTES 49152          // A 16KB + B 32KB
#define SMEM_TOTAL_GEMM (STAGES * STAGE_BYTES)

__device__ __forceinline__ void load_stage(uint32_t sb, int stage, int c, int m0, int n0) {
    // chunk -> K offsets for the 3 products: hh, hl, lh
    int a_off = (c < 12) ? c * 64 : ((c < 24) ? (c - 12) * 64 : DIN + (c - 24) * 64);
    int b_off = (c < 12) ? c * 64 : ((c < 24) ? DIN + (c - 12) * 64 : (c - 24) * 64);
    uint32_t abase = sb + stage * STAGE_BYTES;
    uint32_t bbase = abase + 16384;
    int tid = threadIdx.x;
    #pragma unroll
    for (int i = 0; i < 4; i++) {               // A: 128 rows x 8 chunks = 1024
        int idx = tid + i * 256;
        int r = idx >> 3, t = idx & 7;
        uint32_t sw = (uint32_t)((t ^ (r & 7)) << 4);
        cp_async16(abase + r * 128 + sw, d_xs + (size_t)(m0 + r) * KSPLIT + a_off + t * 8);
    }
    #pragma unroll
    for (int i = 0; i < 8; i++) {               // B: 256 rows x 8 chunks = 2048
        int idx = tid + i * 256;
        int r = idx >> 3, t = idx & 7;
        uint32_t sw = (uint32_t)((t ^ (r & 7)) << 4);
        cp_async16(bbase + r * 128 + sw, d_ws + (size_t)(n0 + r) * KSPLIT + b_off + t * 8);
    }
}

__device__ __forceinline__ void ldmx4(uint32_t& r0, uint32_t& r1, uint32_t& r2,
                                      uint32_t& r3, uint32_t addr) {
    asm volatile("ldmatrix.sync.aligned.m8n8.x4.shared.b16 {%0,%1,%2,%3}, [%4];"
                 : "=r"(r0), "=r"(r1), "=r"(r2), "=r"(r3) : "r"(addr));
}

__device__ __forceinline__ void mma16816(float* c, const uint32_t* a, const uint32_t* b) {
    asm volatile(
        "mma.sync.aligned.m16n8k16.row.col.f32.bf16.bf16.f32 "
        "{%0,%1,%2,%3}, {%4,%5,%6,%7}, {%8,%9}, {%0,%1,%2,%3};"
        : "+f"(c[0]), "+f"(c[1]), "+f"(c[2]), "+f"(c[3])
        : "r"(a[0]), "r"(a[1]), "r"(a[2]), "r"(a[3]), "r"(b[0]), "r"(b[1]));
}

__global__ __launch_bounds__(256) void gemm_mma_kernel() {
    extern __shared__ __align__(1024) char smem[];
    uint32_t sb = smem_u32(smem);
    const int tid  = threadIdx.x;
    const int wid  = tid >> 5, lane = tid & 31;
    const int n0 = blockIdx.x * 256;
    const int m0 = blockIdx.y * 128;
    const int wm = (wid & 1) * 64;        // warp M offset
    const int wn = (wid >> 1) * 64;       // warp N offset

    // lane-derived ldmatrix row selectors
    const int q  = lane >> 3;             // matrix index 0..3
    const int rq = lane & 7;              // row within 8x8 matrix
    const int a_rowl   = (q & 1) * 8 + rq;   // A: row-local within m16
    const int a_chunkq = q >> 1;             // A: k8 selector
    const int b_rowl   = (q >> 1) * 8 + rq;  // B: n-local within n16
    const int b_chunkq = q & 1;              // B: k8 selector

    float acc[4][8][4];
    #pragma unroll
    for (int i = 0; i < 4; i++)
        #pragma unroll
        for (int j = 0; j < 8; j++)
            #pragma unroll
            for (int v = 0; v < 4; v++) acc[i][j][v] = 0.f;

    // prologue: fill 3 stages
    #pragma unroll
    for (int p = 0; p < STAGES; ++p) {
        load_stage(sb, p, p, m0, n0);
        asm volatile("cp.async.commit_group;" ::: "memory");
    }

    for (int c = 0; c < NCHUNK; ++c) {
        int s = c % STAGES;
        asm volatile("cp.async.wait_group 2;" ::: "memory");
        __syncthreads();
        uint32_t Ab = sb + s * STAGE_BYTES;
        uint32_t Bb = Ab + 16384;

        #pragma unroll
        for (int ks = 0; ks < 4; ++ks) {
            uint32_t a[4][4];
            uint32_t b[8][2];
            #pragma unroll
            for (int mi = 0; mi < 4; ++mi) {
                int row = wm + mi * 16 + a_rowl;
                uint32_t addr = Ab + row * 128 +
                                (uint32_t)(((ks * 2 + a_chunkq) ^ (row & 7)) << 4);
                ldmx4(a[mi][0], a[mi][1], a[mi][2], a[mi][3], addr);
            }
            #pragma unroll
            for (int nj = 0; nj < 4; ++nj) {
                int n = wn + nj * 16 + b_rowl;
                uint32_t addr = Bb + n * 128 +
                                (uint32_t)(((ks * 2 + b_chunkq) ^ (n & 7)) << 4);
                uint32_t r0, r1, r2, r3;
                ldmx4(r0, r1, r2, r3, addr);
                b[nj * 2 + 0][0] = r0; b[nj * 2 + 0][1] = r1;
                b[nj * 2 + 1][0] = r2; b[nj * 2 + 1][1] = r3;
            }
            #pragma unroll
            for (int mi = 0; mi < 4; ++mi)
                #pragma unroll
                for (int nj = 0; nj < 8; ++nj)
                    mma16816(acc[mi][nj], a[mi], b[nj]);
        }
        __syncthreads();
        int cn = c + STAGES;
        if (cn < NCHUNK) load_stage(sb, s, cn, m0, n0);
        asm volatile("cp.async.commit_group;" ::: "memory");
    }

    // epilogue
    const int erow = lane >> 2;
    const int ecol = (lane & 3) * 2;
    #pragma unroll
    for (int mi = 0; mi < 4; ++mi) {
        #pragma unroll
        for (int nj = 0; nj < 8; ++nj) {
            int gr = m0 + wm + mi * 16 + erow;
            int gc = n0 + wn + nj * 8 + ecol;
            float* o0 = &d_h0[(size_t)gr * HH + gc];
            o0[0] = acc[mi][nj][0];
            o0[1] = acc[mi][nj][1];
            float* o1 = &d_h0[(size_t)(gr + 8) * HH + gc];
            o1[0] = acc[mi][nj][2];
            o1[1] = acc[mi][nj][3];
        }
    }
}

// ---------------- fused gather: agg + self + bias + relu + score dots -------
__global__ __launch_bounds__(128) void gather_kernel(
    const float* __restrict__ gcn_b, const float* __restrict__ w1,
    const float* __restrict__ w2,    const float* __restrict__ sag_b) {
    __shared__ float red[8];   // 4 warps x {a,b}
    int n = blockIdx.x;
    int tid = threadIdx.x;
    int lane = tid & 31, w = tid >> 5;
    int beg = d_rowptr[n], end = d_rowptr[n + 1];
    float din = d_dinv[n];
    int f = tid * 4;

    float4 hv = *(const float4*)&d_h0[(size_t)n * HH + f];
    float d2 = din * din;
    float4 acc = make_float4(hv.x * d2, hv.y * d2, hv.z * d2, hv.w * d2);

    for (int j = beg; j < end; ++j) {
        int s = d_esrc[j];
        float c = d_dinv[s] * din;
        float4 xv = *(const float4*)&d_h0[(size_t)s * HH + f];
        acc.x += xv.x * c;
        acc.y += xv.y * c;
        acc.z += xv.z * c;
        acc.w += xv.w * c;
    }
    float4 bv = *(const float4*)&gcn_b[f];
    acc.x = fmaxf(acc.x + bv.x, 0.f);
    acc.y = fmaxf(acc.y + bv.y, 0.f);
    acc.z = fmaxf(acc.z + bv.z, 0.f);
    acc.w = fmaxf(acc.w + bv.w, 0.f);
    *(float4*)&d_h[(size_t)n * HH + f] = acc;

    // score dots
    float4 w1v = *(const float4*)&w1[f];
    float4 w2v = *(const float4*)&w2[f];
    float a = acc.x * w1v.x + acc.y * w1v.y + acc.z * w1v.z + acc.w * w1v.w;
    float b = acc.x * w2v.x + acc.y * w2v.y + acc.z * w2v.z + acc.w * w2v.w;
    #pragma unroll
    for (int o = 16; o > 0; o >>= 1) {
        a += __shfl_down_sync(0xffffffffu, a, o);
        b += __shfl_down_sync(0xffffffffu, b, o);
    }
    if (lane == 0) { red[w] = a; red[w + 4] = b; }
    __syncthreads();
    if (tid == 0) {
        d_s[n]  = red[0] + red[1] + red[2] + red[3] + sag_b[0];
        d_s2[n] = red[4] + red[5] + red[6] + red[7];
    }
}

__global__ void score_edge_kernel(const int* __restrict__ src, const int* __restrict__ dst) {
    int e = blockIdx.x * blockDim.x + threadIdx.x;
    if (e < EE) atomicAdd(&d_s[dst[e]], d_s2[src[e]]);
}

// ---------------- per-graph top-250 of 500 (bitonic, stable ties) -----------
__global__ __launch_bounds__(256) void topk_kernel() {
    __shared__ float key[512];
    __shared__ int   kid[512];
    int g = blockIdx.x;
    for (int i = threadIdx.x; i < 512; i += 256) {
        if (i < NPGc) { key[i] = d_s[g * NPGc + i]; kid[i] = i; }
        else          { key[i] = -FLT_MAX;          kid[i] = i; }
    }
    for (int k = 2; k <= 512; k <<= 1) {
        for (int j = k >> 1; j > 0; j >>= 1) {
            __syncthreads();
            for (int t = threadIdx.x; t < 512; t += 256) {
                int p = t ^ j;
                if (p > t) {
                    float ka = key[t], kb = key[p];
                    int   ia = kid[t], ib = kid[p];
                    bool b_gt_a = (kb > ka) || (kb == ka && ib < ia);
                    bool desc = ((t & k) == 0);
                    bool do_swap = desc ? b_gt_a : (!b_gt_a && (ka != kb || ia != ib));
                    if (do_swap) {
                        key[t] = kb; key[p] = ka;
                        kid[t] = ib; kid[p] = ia;
                    }
                }
            }
        }
    }
    __syncthreads();
    for (int i = threadIdx.x; i < KKc; i += 256) {
        d_gidx[g * KKc + i] = g * NPGc + kid[i];
        d_tval[g * KKc + i] = tanhf(key[i]);
    }
}

// ---------------- pooled sums + global sum of squares -----------------------
__global__ __launch_bounds__(256) void pool_kernel() {
    __shared__ int   sg[KKc];
    __shared__ float st[KKc];
    int g = blockIdx.x;
    int tid = threadIdx.x;
    if (tid < KKc) { sg[tid] = d_gidx[g * KKc + tid]; st[tid] = d_tval[g * KKc + tid]; }
    __syncthreads();

    int f1 = tid, f2 = tid + 256;
    float s1 = 0.f, q1 = 0.f, s2 = 0.f, q2 = 0.f;
    for (int k = 0; k < KKc; k++) {
        const float* hr = &d_h[(size_t)sg[k] * HH];
        float t = st[k];
        float v1 = hr[f1] * t;
        float v2 = hr[f2] * t;
        s1 += v1; q1 += v1 * v1;
        s2 += v2; q2 += v2 * v2;
    }
    d_S[g * HH + f1] = s1;
    d_S[g * HH + f2] = s2;
    atomicAdd(&d_ssq[f1], q1);
    atomicAdd(&d_ssq[f2], q2);
}

// ---------------- BN (fused) + mean-pool + FC + log_softmax -----------------
__global__ __launch_bounds__(512) void final_kernel(
    const float* __restrict__ gamma, const float* __restrict__ beta,
    const float* __restrict__ fc_w,  const float* __restrict__ fc_b,
    float* __restrict__ out) {
    __shared__ float mu[HH], rstd[HH], lg[GG * CC];
    int tid = threadIdx.x;
    {
        int f = tid;
        float cs = 0.f;
        for (int g = 0; g < GG; g++) cs += d_S[g * HH + f];
        float m = cs * (1.0f / (GG * KKc));
        float var = d_ssq[f] * (1.0f / (GG * KKc)) - m * m;
        mu[f] = m;
        rstd[f] = rsqrtf(var + EPSc);
    }
    __syncthreads();
    {
        int g = tid >> 2, c = tid & 3;
        float acc = fc_b[c];
        for (int f = 0; f < HH; f++) {
            float pooled = (d_S[g * HH + f] * (1.0f / KKc) - mu[f]) * rstd[f] * gamma[f] + beta[f];
            acc += pooled * fc_w[f * CC + c];
        }
        lg[tid] = acc;
    }
    __syncthreads();
    if (tid < GG) {
        float l0 = lg[tid * 4 + 0], l1 = lg[tid * 4 + 1];
        float l2 = lg[tid * 4 + 2], l3 = lg[tid * 4 + 3];
        float m = fmaxf(fmaxf(l0, l1), fmaxf(l2, l3));
        float lse = m + logf(expf(l0 - m) + expf(l1 - m) + expf(l2 - m) + expf(l3 - m));
        out[tid * 4 + 0] = l0 - lse;
        out[tid * 4 + 1] = l1 - lse;
        out[tid * 4 + 2] = l2 - lse;
        out[tid * 4 + 3] = l3 - lse;
    }
}

// ---------------- launch ----------------
extern "C" void kernel_launch(void* const* d_in, const int* in_sizes, int n_in,
                              void* d_out, int out_size) {
    const float* x      = (const float*)d_in[0];
    const float* gcn_w  = (const float*)d_in[1];
    const float* gcn_b  = (const float*)d_in[2];
    const float* sag_w1 = (const float*)d_in[3];
    const float* sag_w2 = (const float*)d_in[4];
    const float* sag_b  = (const float*)d_in[5];
    const float* bn_g   = (const float*)d_in[6];
    const float* bn_b   = (const float*)d_in[7];
    const float* fc_w   = (const float*)d_in[8];
    const float* fc_b   = (const float*)d_in[9];
    const int*   ei     = (const int*)d_in[10];
    const int* src = ei;
    const int* dst = ei + EE;
    float* out = (float*)d_out;

    cudaFuncSetAttribute(gemm_mma_kernel, cudaFuncAttributeMaxDynamicSharedMemorySize,
                         SMEM_TOTAL_GEMM);

    init_kernel<<<(NN + 255) / 256, 256>>>();
    csr_count_kernel<<<(EE + 255) / 256, 256>>>(dst);
    csr_scan_kernel<<<1, 1024>>>();
    csr_fill_kernel<<<(EE + 255) / 256, 256>>>(src, dst);
    convert_w_kernel<<<(DIN * HH) / 256, 256>>>(gcn_w);
    convert_x_kernel<<<(NN * DIN) / 256, 256>>>(x);
    gemm_mma_kernel<<<dim3(HH / 256, NN / 128), 256, SMEM_TOTAL_GEMM>>>();
    gather_kernel<<<NN, 128>>>(gcn_b, sag_w1, sag_w2, sag_b);
    score_edge_kernel<<<(EE + 255) / 256, 256>>>(src, dst);
    topk_kernel<<<GG, 256>>>();
    pool_kernel<<<GG, 256>>>();
    final_kernel<<<1, 512>>>(bn_g, bn_b, fc_w, fc_b, out);
}

// round 7
// speedup vs baseline: 2.1112x; 1.0726x over previous
#include <cuda_runtime.h>
#include <cuda_bf16.h>
#include <math.h>
#include <float.h>
#include <stdint.h>

// Problem constants (fixed shapes)
#define NN   64000      // nodes
#define NPGc 500        // nodes per graph
#define GG   128        // graphs
#define EE   131072     // edges
#define DIN  768        // input dim
#define HH   512        // hidden
#define CC   4          // classes
#define KKc  250        // kept nodes per graph
#define EPSc 1e-5f

// split-GEMM: 12 super-chunks of K=64; each does 3 products (Ah*Bh, Al*Bh, Ah*Bl)
#define KSPLIT   1536   // row stride of split buffers (hi 768 | lo 768)
#define NSUPER   12
#define STAGES   2

// ---------------- scratch (static device globals; no allocation) -------------
__device__ float d_dinv[NN];
__device__ int   d_cnt[NN];
__device__ int   d_rowptr[NN + 1];
__device__ int   d_cur[NN];
__device__ int   d_esrc[EE];
__device__ float d_h0[NN * HH];
__device__ float d_h [NN * HH];
__device__ float d_s2[NN];
__device__ float d_s [NN];
__device__ int   d_gidx[GG * KKc];
__device__ float d_tval[GG * KKc];
__device__ float d_S  [GG * HH];
__device__ float d_ssq[HH];
__device__ __nv_bfloat16 d_xs[(size_t)NN * KSPLIT];   // x split: [m][hi 768 | lo 768]
__device__ __nv_bfloat16 d_ws[(size_t)HH * KSPLIT];   // W^T split: [n][hi 768 | lo 768]

__device__ __forceinline__ uint32_t smem_u32(const void* p) {
    uint32_t a;
    asm("{ .reg .u64 t; cvta.to.shared.u64 t, %1; cvt.u32.u64 %0, t; }" : "=r"(a) : "l"(p));
    return a;
}

__device__ __forceinline__ void cp_async16(uint32_t dst, const void* src) {
    asm volatile("cp.async.cg.shared.global [%0], [%1], 16;" :: "r"(dst), "l"(src));
}

// ---------------- init ----------------
__global__ void init_kernel() {
    int i = blockIdx.x * blockDim.x + threadIdx.x;
    if (i < NN) d_cnt[i] = 0;
    if (i < HH) d_ssq[i] = 0.0f;
}

// ---------------- CSR build ----------------
__global__ void csr_count_kernel(const int* __restrict__ dst) {
    int e = blockIdx.x * blockDim.x + threadIdx.x;
    if (e < EE) atomicAdd(&d_cnt[dst[e]], 1);
}

__global__ __launch_bounds__(1024) void csr_scan_kernel() {
    __shared__ int wsum[32];
    __shared__ int chunk_total;
    int tid = threadIdx.x;
    int lane = tid & 31, w = tid >> 5;
    int running = 0;
    for (int base = 0; base < NN; base += 1024) {
        int i = base + tid;
        int v = (i < NN) ? d_cnt[i] : 0;
        int incl = v;
        #pragma unroll
        for (int o = 1; o < 32; o <<= 1) {
            int t = __shfl_up_sync(0xffffffffu, incl, o);
            if (lane >= o) incl += t;
        }
        if (lane == 31) wsum[w] = incl;
        __syncthreads();
        if (w == 0) {
            int s = wsum[lane];
            #pragma unroll
            for (int o = 1; o < 32; o <<= 1) {
                int t = __shfl_up_sync(0xffffffffu, s, o);
                if (lane >= o) s += t;
            }
            wsum[lane] = s;
            if (lane == 31) chunk_total = s;
        }
        __syncthreads();
        int excl = running + (w > 0 ? wsum[w - 1] : 0) + incl - v;
        if (i < NN) {
            d_rowptr[i] = excl;
            d_cur[i]    = excl;
            d_dinv[i]   = rsqrtf(1.0f + (float)v);   // self-loop degree
        }
        running += chunk_total;
        __syncthreads();
    }
    if (tid == 0) d_rowptr[NN] = EE;
}

__global__ void csr_fill_kernel(const int* __restrict__ src, const int* __restrict__ dst) {
    int e = blockIdx.x * blockDim.x + threadIdx.x;
    if (e < EE) {
        int pos = atomicAdd(&d_cur[dst[e]], 1);
        d_esrc[pos] = src[e];
    }
}

// ---------------- split conversion ----------------
__global__ void convert_x_kernel(const float* __restrict__ x) {
    int i = blockIdx.x * blockDim.x + threadIdx.x;   // NN*DIN threads
    int m = i / DIN, k = i - m * DIN;
    float v = x[i];
    __nv_bfloat16 hi = __float2bfloat16(v);
    __nv_bfloat16 lo = __float2bfloat16(v - __bfloat162float(hi));
    d_xs[(size_t)m * KSPLIT + k] = hi;
    d_xs[(size_t)m * KSPLIT + DIN + k] = lo;
}

__global__ void convert_w_kernel(const float* __restrict__ w) {
    int i = blockIdx.x * blockDim.x + threadIdx.x;   // DIN*HH threads
    int k = i / HH, n = i - k * HH;
    float v = w[i];
    __nv_bfloat16 hi = __float2bfloat16(v);
    __nv_bfloat16 lo = __float2bfloat16(v - __bfloat162float(hi));
    d_ws[(size_t)n * KSPLIT + k] = hi;
    d_ws[(size_t)n * KSPLIT + DIN + k] = lo;
}

// ---------------- HMMA GEMM: h0 = x @ W  (bf16 split, shared tiles) ---------
// CTA tile 128(M) x 256(N). Per super-chunk: A-hi 16K, A-lo 16K, B-hi 32K,
// B-lo 32K = 96KB/stage, 2 stages. 8 warps: 2(M) x 4(N), warp tile 64x64.
#define STAGE_BYTES 98304
#define SMEM_TOTAL_GEMM (STAGES * STAGE_BYTES)
#define AHI_OFF 0
#define ALO_OFF 16384
#define BHI_OFF 32768
#define BLO_OFF 65536

__device__ __forceinline__ void load_super(uint32_t sb, int stage, int sc, int m0, int n0) {
    int k64 = sc * 64;
    uint32_t base = sb + stage * STAGE_BYTES;
    int tid = threadIdx.x;
    #pragma unroll
    for (int i = 0; i < 4; i++) {               // A: 128 rows x 8 chunks
        int idx = tid + i * 256;
        int r = idx >> 3, t = idx & 7;
        uint32_t sw = (uint32_t)(r * 128 + ((t ^ (r & 7)) << 4));
        const __nv_bfloat16* arow = d_xs + (size_t)(m0 + r) * KSPLIT + k64 + t * 8;
        cp_async16(base + AHI_OFF + sw, arow);
        cp_async16(base + ALO_OFF + sw, arow + DIN);
    }
    #pragma unroll
    for (int i = 0; i < 8; i++) {               // B: 256 rows x 8 chunks
        int idx = tid + i * 256;
        int r = idx >> 3, t = idx & 7;
        uint32_t sw = (uint32_t)(r * 128 + ((t ^ (r & 7)) << 4));
        const __nv_bfloat16* brow = d_ws + (size_t)(n0 + r) * KSPLIT + k64 + t * 8;
        cp_async16(base + BHI_OFF + sw, brow);
        cp_async16(base + BLO_OFF + sw, brow + DIN);
    }
}

__device__ __forceinline__ void ldmx4(uint32_t& r0, uint32_t& r1, uint32_t& r2,
                                      uint32_t& r3, uint32_t addr) {
    asm volatile("ldmatrix.sync.aligned.m8n8.x4.shared.b16 {%0,%1,%2,%3}, [%4];"
                 : "=r"(r0), "=r"(r1), "=r"(r2), "=r"(r3) : "r"(addr));
}

__device__ __forceinline__ void mma16816(float* c, const uint32_t* a, const uint32_t* b) {
    asm volatile(
        "mma.sync.aligned.m16n8k16.row.col.f32.bf16.bf16.f32 "
        "{%0,%1,%2,%3}, {%4,%5,%6,%7}, {%8,%9}, {%0,%1,%2,%3};"
        : "+f"(c[0]), "+f"(c[1]), "+f"(c[2]), "+f"(c[3])
        : "r"(a[0]), "r"(a[1]), "r"(a[2]), "r"(a[3]), "r"(b[0]), "r"(b[1]));
}

__global__ __launch_bounds__(256) void gemm_mma_kernel() {
    extern __shared__ __align__(1024) char smem[];
    uint32_t sb = smem_u32(smem);
    const int tid  = threadIdx.x;
    const int wid  = tid >> 5, lane = tid & 31;
    const int n0 = blockIdx.x * 256;
    const int m0 = blockIdx.y * 128;
    const int wm = (wid & 1) * 64;        // warp M offset
    const int wn = (wid >> 1) * 64;       // warp N offset

    const int q  = lane >> 3;             // ldmatrix matrix index 0..3
    const int rq = lane & 7;
    const int a_rowl   = (q & 1) * 8 + rq;
    const int a_chunkq = q >> 1;
    const int b_rowl   = (q >> 1) * 8 + rq;
    const int b_chunkq = q & 1;

    float acc[4][8][4];
    #pragma unroll
    for (int i = 0; i < 4; i++)
        #pragma unroll
        for (int j = 0; j < 8; j++)
            #pragma unroll
            for (int v = 0; v < 4; v++) acc[i][j][v] = 0.f;

    // prologue: fill 2 stages
    #pragma unroll
    for (int p = 0; p < STAGES; ++p) {
        load_super(sb, p, p, m0, n0);
        asm volatile("cp.async.commit_group;" ::: "memory");
    }

    for (int sc = 0; sc < NSUPER; ++sc) {
        int s = sc & 1;
        asm volatile("cp.async.wait_group 1;" ::: "memory");
        __syncthreads();
        uint32_t base = sb + s * STAGE_BYTES;

        #pragma unroll
        for (int ks = 0; ks < 4; ++ks) {
            uint32_t ah[4][4], al[4][4];
            uint32_t b[8][2];
            // A-hi frags
            #pragma unroll
            for (int mi = 0; mi < 4; ++mi) {
                int row = wm + mi * 16 + a_rowl;
                uint32_t addr = base + AHI_OFF + row * 128 +
                                (uint32_t)(((ks * 2 + a_chunkq) ^ (row & 7)) << 4);
                ldmx4(ah[mi][0], ah[mi][1], ah[mi][2], ah[mi][3], addr);
            }
            // B-hi frags
            #pragma unroll
            for (int nj = 0; nj < 4; ++nj) {
                int n = wn + nj * 16 + b_rowl;
                uint32_t addr = base + BHI_OFF + n * 128 +
                                (uint32_t)(((ks * 2 + b_chunkq) ^ (n & 7)) << 4);
                uint32_t r0, r1, r2, r3;
                ldmx4(r0, r1, r2, r3, addr);
                b[nj * 2 + 0][0] = r0; b[nj * 2 + 0][1] = r1;
                b[nj * 2 + 1][0] = r2; b[nj * 2 + 1][1] = r3;
            }
            // Ah x Bh
            #pragma unroll
            for (int mi = 0; mi < 4; ++mi)
                #pragma unroll
                for (int nj = 0; nj < 8; ++nj)
                    mma16816(acc[mi][nj], ah[mi], b[nj]);
            // A-lo frags ; Al x Bh
            #pragma unroll
            for (int mi = 0; mi < 4; ++mi) {
                int row = wm + mi * 16 + a_rowl;
                uint32_t addr = base + ALO_OFF + row * 128 +
                                (uint32_t)(((ks * 2 + a_chunkq) ^ (row & 7)) << 4);
                ldmx4(al[mi][0], al[mi][1], al[mi][2], al[mi][3], addr);
            }
            #pragma unroll
            for (int mi = 0; mi < 4; ++mi)
                #pragma unroll
                for (int nj = 0; nj < 8; ++nj)
                    mma16816(acc[mi][nj], al[mi], b[nj]);
            // B-lo frags (overwrite b) ; Ah x Bl
            #pragma unroll
            for (int nj = 0; nj < 4; ++nj) {
                int n = wn + nj * 16 + b_rowl;
                uint32_t addr = base + BLO_OFF + n * 128 +
                                (uint32_t)(((ks * 2 + b_chunkq) ^ (n & 7)) << 4);
                uint32_t r0, r1, r2, r3;
                ldmx4(r0, r1, r2, r3, addr);
                b[nj * 2 + 0][0] = r0; b[nj * 2 + 0][1] = r1;
                b[nj * 2 + 1][0] = r2; b[nj * 2 + 1][1] = r3;
            }
            #pragma unroll
            for (int mi = 0; mi < 4; ++mi)
                #pragma unroll
                for (int nj = 0; nj < 8; ++nj)
                    mma16816(acc[mi][nj], ah[mi], b[nj]);
        }
        __syncthreads();
        int cn = sc + STAGES;
        if (cn < NSUPER) load_super(sb, s, cn, m0, n0);
        asm volatile("cp.async.commit_group;" ::: "memory");
    }

    // epilogue
    const int erow = lane >> 2;
    const int ecol = (lane & 3) * 2;
    #pragma unroll
    for (int mi = 0; mi < 4; ++mi) {
        #pragma unroll
        for (int nj = 0; nj < 8; ++nj) {
            int gr = m0 + wm + mi * 16 + erow;
            int gc = n0 + wn + nj * 8 + ecol;
            float* o0 = &d_h0[(size_t)gr * HH + gc];
            o0[0] = acc[mi][nj][0];
            o0[1] = acc[mi][nj][1];
            float* o1 = &d_h0[(size_t)(gr + 8) * HH + gc];
            o1[0] = acc[mi][nj][2];
            o1[1] = acc[mi][nj][3];
        }
    }
}

// ---------------- fused gather: agg + self + bias + relu + score dots -------
__global__ __launch_bounds__(128) void gather_kernel(
    const float* __restrict__ gcn_b, const float* __restrict__ w1,
    const float* __restrict__ w2,    const float* __restrict__ sag_b) {
    __shared__ float red[8];   // 4 warps x {a,b}
    int n = blockIdx.x;
    int tid = threadIdx.x;
    int lane = tid & 31, w = tid >> 5;
    int beg = d_rowptr[n], end = d_rowptr[n + 1];
    float din = d_dinv[n];
    int f = tid * 4;

    float4 hv = *(const float4*)&d_h0[(size_t)n * HH + f];
    float d2 = din * din;
    float4 acc = make_float4(hv.x * d2, hv.y * d2, hv.z * d2, hv.w * d2);

    for (int j = beg; j < end; ++j) {
        int s = d_esrc[j];
        float c = d_dinv[s] * din;
        float4 xv = *(const float4*)&d_h0[(size_t)s * HH + f];
        acc.x += xv.x * c;
        acc.y += xv.y * c;
        acc.z += xv.z * c;
        acc.w += xv.w * c;
    }
    float4 bv = *(const float4*)&gcn_b[f];
    acc.x = fmaxf(acc.x + bv.x, 0.f);
    acc.y = fmaxf(acc.y + bv.y, 0.f);
    acc.z = fmaxf(acc.z + bv.z, 0.f);
    acc.w = fmaxf(acc.w + bv.w, 0.f);
    *(float4*)&d_h[(size_t)n * HH + f] = acc;

    // score dots
    float4 w1v = *(const float4*)&w1[f];
    float4 w2v = *(const float4*)&w2[f];
    float a = acc.x * w1v.x + acc.y * w1v.y + acc.z * w1v.z + acc.w * w1v.w;
    float b = acc.x * w2v.x + acc.y * w2v.y + acc.z * w2v.z + acc.w * w2v.w;
    #pragma unroll
    for (int o = 16; o > 0; o >>= 1) {
        a += __shfl_down_sync(0xffffffffu, a, o);
        b += __shfl_down_sync(0xffffffffu, b, o);
    }
    if (lane == 0) { red[w] = a; red[w + 4] = b; }
    __syncthreads();
    if (tid == 0) {
        d_s[n]  = red[0] + red[1] + red[2] + red[3] + sag_b[0];
        d_s2[n] = red[4] + red[5] + red[6] + red[7];
    }
}

__global__ void score_edge_kernel(const int* __restrict__ src, const int* __restrict__ dst) {
    int e = blockIdx.x * blockDim.x + threadIdx.x;
    if (e < EE) atomicAdd(&d_s[dst[e]], d_s2[src[e]]);
}

// ---------------- per-graph top-250 of 500 (bitonic, stable ties) -----------
__global__ __launch_bounds__(256) void topk_kernel() {
    __shared__ float key[512];
    __shared__ int   kid[512];
    int g = blockIdx.x;
    for (int i = threadIdx.x; i < 512; i += 256) {
        if (i < NPGc) { key[i] = d_s[g * NPGc + i]; kid[i] = i; }
        else          { key[i] = -FLT_MAX;          kid[i] = i; }
    }
    for (int k = 2; k <= 512; k <<= 1) {
        for (int j = k >> 1; j > 0; j >>= 1) {
            __syncthreads();
            for (int t = threadIdx.x; t < 512; t += 256) {
                int p = t ^ j;
                if (p > t) {
                    float ka = key[t], kb = key[p];
                    int   ia = kid[t], ib = kid[p];
                    bool b_gt_a = (kb > ka) || (kb == ka && ib < ia);
                    bool desc = ((t & k) == 0);
                    bool do_swap = desc ? b_gt_a : (!b_gt_a && (ka != kb || ia != ib));
                    if (do_swap) {
                        key[t] = kb; key[p] = ka;
                        kid[t] = ib; kid[p] = ia;
                    }
                }
            }
        }
    }
    __syncthreads();
    for (int i = threadIdx.x; i < KKc; i += 256) {
        d_gidx[g * KKc + i] = g * NPGc + kid[i];
        d_tval[g * KKc + i] = tanhf(key[i]);
    }
}

// ---------------- pooled sums + global sum of squares -----------------------
__global__ __launch_bounds__(256) void pool_kernel() {
    __shared__ int   sg[KKc];
    __shared__ float st[KKc];
    int g = blockIdx.x;
    int tid = threadIdx.x;
    if (tid < KKc) { sg[tid] = d_gidx[g * KKc + tid]; st[tid] = d_tval[g * KKc + tid]; }
    __syncthreads();

    int f1 = tid, f2 = tid + 256;
    float s1 = 0.f, q1 = 0.f, s2 = 0.f, q2 = 0.f;
    for (int k = 0; k < KKc; k++) {
        const float* hr = &d_h[(size_t)sg[k] * HH];
        float t = st[k];
        float v1 = hr[f1] * t;
        float v2 = hr[f2] * t;
        s1 += v1; q1 += v1 * v1;
        s2 += v2; q2 += v2 * v2;
    }
    d_S[g * HH + f1] = s1;
    d_S[g * HH + f2] = s2;
    atomicAdd(&d_ssq[f1], q1);
    atomicAdd(&d_ssq[f2], q2);
}

// ---------------- BN (fused) + mean-pool + FC + log_softmax -----------------
__global__ __launch_bounds__(512) void final_kernel(
    const float* __restrict__ gamma, const float* __restrict__ beta,
    const float* __restrict__ fc_w,  const float* __restrict__ fc_b,
    float* __restrict__ out) {
    __shared__ float mu[HH], rstd[HH], lg[GG * CC];
    int tid = threadIdx.x;
    {
        int f = tid;
        float cs = 0.f;
        for (int g = 0; g < GG; g++) cs += d_S[g * HH + f];
        float m = cs * (1.0f / (GG * KKc));
        float var = d_ssq[f] * (1.0f / (GG * KKc)) - m * m;
        mu[f] = m;
        rstd[f] = rsqrtf(var + EPSc);
    }
    __syncthreads();
    {
        int g = tid >> 2, c = tid & 3;
        float acc = fc_b[c];
        for (int f = 0; f < HH; f++) {
            float pooled = (d_S[g * HH + f] * (1.0f / KKc) - mu[f]) * rstd[f] * gamma[f] + beta[f];
            acc += pooled * fc_w[f * CC + c];
        }
        lg[tid] = acc;
    }
    __syncthreads();
    if (tid < GG) {
        float l0 = lg[tid * 4 + 0], l1 = lg[tid * 4 + 1];
        float l2 = lg[tid * 4 + 2], l3 = lg[tid * 4 + 3];
        float m = fmaxf(fmaxf(l0, l1), fmaxf(l2, l3));
        float lse = m + logf(expf(l0 - m) + expf(l1 - m) + expf(l2 - m) + expf(l3 - m));
        out[tid * 4 + 0] = l0 - lse;
        out[tid * 4 + 1] = l1 - lse;
        out[tid * 4 + 2] = l2 - lse;
        out[tid * 4 + 3] = l3 - lse;
    }
}

// ---------------- launch ----------------
extern "C" void kernel_launch(void* const* d_in, const int* in_sizes, int n_in,
                              void* d_out, int out_size) {
    const float* x      = (const float*)d_in[0];
    const float* gcn_w  = (const float*)d_in[1];
    const float* gcn_b  = (const float*)d_in[2];
    const float* sag_w1 = (const float*)d_in[3];
    const float* sag_w2 = (const float*)d_in[4];
    const float* sag_b  = (const float*)d_in[5];
    const float* bn_g   = (const float*)d_in[6];
    const float* bn_b   = (const float*)d_in[7];
    const float* fc_w   = (const float*)d_in[8];
    const float* fc_b   = (const float*)d_in[9];
    const int*   ei     = (const int*)d_in[10];
    const int* src = ei;
    const int* dst = ei + EE;
    float* out = (float*)d_out;

    cudaFuncSetAttribute(gemm_mma_kernel, cudaFuncAttributeMaxDynamicSharedMemorySize,
                         SMEM_TOTAL_GEMM);

    // launch order chosen so gemm is the 4th launch (ncu capture lands there)
    convert_w_kernel<<<(DIN * HH) / 256, 256>>>(gcn_w);
    init_kernel<<<(NN + 255) / 256, 256>>>();
    convert_x_kernel<<<(NN * DIN) / 256, 256>>>(x);
    gemm_mma_kernel<<<dim3(HH / 256, NN / 128), 256, SMEM_TOTAL_GEMM>>>();
    csr_count_kernel<<<(EE + 255) / 256, 256>>>(dst);
    csr_scan_kernel<<<1, 1024>>>();
    csr_fill_kernel<<<(EE + 255) / 256, 256>>>(src, dst);
    gather_kernel<<<NN, 128>>>(gcn_b, sag_w1, sag_w2, sag_b);
    score_edge_kernel<<<(EE + 255) / 256, 256>>>(src, dst);
    topk_kernel<<<GG, 256>>>();
    pool_kernel<<<GG, 256>>>();
    final_kernel<<<1, 512>>>(bn_g, bn_b, fc_w, fc_b, out);
}